// round 1
// baseline (speedup 1.0000x reference)
#include <cuda_runtime.h>
#include <cuda_bf16.h>

#define NX   512
#define NPTS 32768
#define CCH  64
#define NB   4

// Block: 256 threads = 8 warps, owns 32 consecutive points (same batch since
// 32768 % 32 == 0). Warp 0 computes per-point weights/offsets into smem; then
// each warp handles 8 channels, lanes map to points (coalesced output writes).
__global__ __launch_bounds__(256) void nu_grid_sample_kernel(
    const float* __restrict__ x,
    const float* __restrict__ coords,
    float* __restrict__ out)
{
    __shared__ float s_w[32][9];
    __shared__ int   s_off[32][9];

    const int p0 = blockIdx.x * 32;      // global point base
    const int b  = p0 / NPTS;
    const int n0 = p0 % NPTS;

    const int tid = threadIdx.x;

    // ---- Phase 1: warp 0 computes weights for the 32 points ----
    if (tid < 32) {
        const int n = n0 + tid;
        const float cy = coords[((size_t)b * NPTS + n) * 2 + 0];
        const float cx = coords[((size_t)b * NPTS + n) * 2 + 1];
        const float posx = cx * 511.0f;
        const float posy = cy * 511.0f;
        const float rx = rintf(posx);    // jnp.round = half-to-even = rintf
        const float ry = rintf(posy);

        float wx[3] = {0.f, 0.f, 0.f};
        float wy[3] = {0.f, 0.f, 0.f};
        #pragma unroll
        for (int j = 0; j < 9; j++) {
            const float o  = 1.5f - 0.375f * (float)j;        // off_n[j], exact in fp32
            const float px = fminf(fmaxf(rx - o, 0.f), 512.f); // clip upper = nx (ref quirk)
            const float py = fminf(fmaxf(ry - o, 0.f), 512.f);
            const float dx = px - posx;
            const float dy = py - posy;
            // _normal constant cancels in normalization: exp(-0.5*(d/0.5)^2)=exp(-2 d^2)
            wx[j / 3] += __expf(-2.f * dx * dx);
            wy[j / 3] += __expf(-2.f * dy * dy);
        }

        float w9[9];
        float s = 0.f;
        #pragma unroll
        for (int a = 0; a < 3; a++)
            #pragma unroll
            for (int c2 = 0; c2 < 3; c2++) {
                const float w = wx[a] * wy[c2];
                w9[a * 3 + c2] = w;
                s += w;
            }
        const float inv = 1.0f / s;

        const int irx = (int)rx;
        const int iry = (int)ry;
        int ixs[3], iys[3];
        #pragma unroll
        for (int a = 0; a < 3; a++) {
            // off_i = [-1, 0, 1]  ->  ix[a] = clip(rx - off_i[a], 0, 511)
            ixs[a] = min(max(irx + 1 - a, 0), NX - 1);
            iys[a] = min(max(iry + 1 - a, 0), NX - 1);
        }

        #pragma unroll
        for (int a = 0; a < 3; a++)
            #pragma unroll
            for (int c2 = 0; c2 < 3; c2++) {
                s_w[tid][a * 3 + c2]   = w9[a * 3 + c2] * inv;
                s_off[tid][a * 3 + c2] = ixs[a] * NX + iys[c2];
            }
    }
    __syncthreads();

    // ---- Phase 2: gather + weighted sum ----
    const int warp = tid >> 5;
    const int lane = tid & 31;

    float w[9];
    int   off[9];
    #pragma unroll
    for (int k = 0; k < 9; k++) {
        w[k]   = s_w[lane][k];    // stride 9 words -> conflict-free across lanes
        off[k] = s_off[lane][k];
    }

    const float* xb = x + (size_t)b * CCH * NX * NX;
    const int    n  = n0 + lane;
    float*       ob = out + (size_t)b * CCH * NPTS + n;

    // Each warp: channels [warp*8, warp*8+8), two at a time for MLP=18.
    #pragma unroll
    for (int cc = 0; cc < 8; cc += 2) {
        const int c0 = warp * 8 + cc;
        const float* pc0 = xb + (size_t)c0 * (NX * NX);
        const float* pc1 = pc0 + (NX * NX);
        float a0 = 0.f, a1 = 0.f;
        #pragma unroll
        for (int k = 0; k < 9; k++) {
            a0 += w[k] * __ldg(pc0 + off[k]);
            a1 += w[k] * __ldg(pc1 + off[k]);
        }
        ob[(size_t)c0 * NPTS]       = a0;   // coalesced: lanes -> consecutive n
        ob[(size_t)(c0 + 1) * NPTS] = a1;
    }
}

extern "C" void kernel_launch(void* const* d_in, const int* in_sizes, int n_in,
                              void* d_out, int out_size) {
    const float* x      = (const float*)d_in[0];
    const float* coords = (const float*)d_in[1];
    // Defensive: metadata order should be (x, coords); swap if sizes say otherwise.
    if (n_in >= 2 && in_sizes[0] == NB * NPTS * 2) {
        const float* t = x; x = coords; coords = t;
    }
    float* out = (float*)d_out;

    const int total_points = NB * NPTS;          // 131072
    const int blocks = total_points / 32;        // 4096
    nu_grid_sample_kernel<<<blocks, 256>>>(x, coords, out);
}

// round 2
// speedup vs baseline: 2.1851x; 2.1851x over previous
#include <cuda_runtime.h>
#include <cuda_bf16.h>

#define NX    512
#define NPTS  32768
#define CCH   64
#define NB    4
#define PLANE (NX * NX)            // 262144 pixels per channel plane
#define BVOL  (PLANE * CCH)        // 16777216 floats per batch (NHWC)

// Scratch: x transposed to NHWC (b, py, px, c). 268 MB device global (bss).
__device__ float g_xt[(size_t)NB * BVOL];

// ---------------------------------------------------------------------------
// Kernel 1: NCHW -> NHWC transpose. Tile = 64 pixels x 64 channels (16 KB smem).
// Grid: NB * (PLANE/64) = 16384 blocks x 256 threads.
// ---------------------------------------------------------------------------
__global__ __launch_bounds__(256) void transpose_kernel(const float* __restrict__ x)
{
    __shared__ float s[64][65];

    const int tile = blockIdx.x;
    const int b    = tile >> 12;              // PLANE/64 = 4096 tiles per batch
    const int p0   = (tile & 4095) * 64;

    const int pl = threadIdx.x & 63;          // pixel within tile
    const int c0 = threadIdx.x >> 6;          // 0..3

    const float* xb = x + (size_t)b * BVOL;   // NCHW batch base
    #pragma unroll
    for (int c = c0; c < 64; c += 4)
        s[c][pl] = xb[(size_t)c * PLANE + p0 + pl];   // 256B coalesced reads

    __syncthreads();

    float* yb = g_xt + (size_t)b * BVOL + (size_t)p0 * CCH;
    #pragma unroll
    for (int i = threadIdx.x; i < 64 * 64; i += 256) {
        const int p = i >> 6;
        const int c = i & 63;
        yb[(size_t)p * CCH + c] = s[c][p];            // 256B coalesced writes
    }
}

// ---------------------------------------------------------------------------
// Kernel 2: gather. Block = 256 threads, owns 32 consecutive points.
// Phase 1: warp 0 computes per-point normalized 3x3 weights + NHWC offsets.
// Phase 2: each warp handles 4 points; per tap one warp-wide 256B float2 load
//          covers all 64 channels. Results staged in smem, written (c,n)-
//          coalesced (32 consecutive n per channel = 128B stores).
// ---------------------------------------------------------------------------
__global__ __launch_bounds__(256) void gather_kernel(
    const float* __restrict__ coords,
    float*       __restrict__ out)
{
    __shared__ float  s_w[32][9];
    __shared__ int    s_off[32][9];       // float offset within NHWC batch
    __shared__ float2 s_out[32][33];      // [channel pair][point], padded

    const int p0g = blockIdx.x * 32;
    const int b   = p0g / NPTS;
    const int n0  = p0g % NPTS;
    const int tid = threadIdx.x;

    // ---- Phase 1: weights (identical math to the passing round-1 kernel) ----
    if (tid < 32) {
        const int   n    = n0 + tid;
        const float cy   = coords[((size_t)b * NPTS + n) * 2 + 0];
        const float cx   = coords[((size_t)b * NPTS + n) * 2 + 1];
        const float posx = cx * 511.0f;
        const float posy = cy * 511.0f;
        const float rx   = rintf(posx);   // jnp.round = half-to-even
        const float ry   = rintf(posy);

        float wx[3] = {0.f, 0.f, 0.f};
        float wy[3] = {0.f, 0.f, 0.f};
        #pragma unroll
        for (int j = 0; j < 9; j++) {
            const float o  = 1.5f - 0.375f * (float)j;          // off_n[j]
            const float px = fminf(fmaxf(rx - o, 0.f), 512.f);  // clip hi = nx (ref quirk)
            const float py = fminf(fmaxf(ry - o, 0.f), 512.f);
            const float dx = px - posx;
            const float dy = py - posy;
            wx[j / 3] += __expf(-2.f * dx * dx);  // normal const cancels in norm
            wy[j / 3] += __expf(-2.f * dy * dy);
        }

        float w9[9];
        float s = 0.f;
        #pragma unroll
        for (int a = 0; a < 3; a++)
            #pragma unroll
            for (int c2 = 0; c2 < 3; c2++) {
                const float w = wx[a] * wy[c2];
                w9[a * 3 + c2] = w;
                s += w;
            }
        const float inv = 1.0f / s;

        const int irx = (int)rx;
        const int iry = (int)ry;
        int ixs[3], iys[3];
        #pragma unroll
        for (int a = 0; a < 3; a++) {
            ixs[a] = min(max(irx + 1 - a, 0), NX - 1);
            iys[a] = min(max(iry + 1 - a, 0), NX - 1);
        }

        #pragma unroll
        for (int a = 0; a < 3; a++)
            #pragma unroll
            for (int c2 = 0; c2 < 3; c2++) {
                s_w[tid][a * 3 + c2]   = w9[a * 3 + c2] * inv;
                s_off[tid][a * 3 + c2] = (ixs[a] * NX + iys[c2]) * CCH;
            }
    }
    __syncthreads();

    // ---- Phase 2: dense NHWC gather ----
    const int lane = tid & 31;
    const int warp = tid >> 5;

    // lane owns channels (2*lane, 2*lane+1)
    const float* base = g_xt + (size_t)b * BVOL + 2 * lane;

    #pragma unroll
    for (int qq = 0; qq < 4; qq += 2) {
        const int q0 = warp * 4 + qq;
        const int q1 = q0 + 1;
        float2 a0 = make_float2(0.f, 0.f);
        float2 a1 = make_float2(0.f, 0.f);
        #pragma unroll
        for (int k = 0; k < 9; k++) {
            const float2 v0 = *(const float2*)(base + s_off[q0][k]);
            const float2 v1 = *(const float2*)(base + s_off[q1][k]);
            const float  w0 = s_w[q0][k];
            const float  w1 = s_w[q1][k];
            a0.x += w0 * v0.x;  a0.y += w0 * v0.y;
            a1.x += w1 * v1.x;  a1.y += w1 * v1.y;
        }
        s_out[lane][q0] = a0;
        s_out[lane][q1] = a1;
    }
    __syncthreads();

    // ---- Phase 3: coalesced (c, n) writes: 128B per channel row ----
    float* ob = out + (size_t)b * CCH * NPTS + n0;
    #pragma unroll
    for (int i = tid; i < CCH * 32; i += 256) {
        const int j = i & 31;         // point within block
        const int c = i >> 5;         // channel
        const float2 v = s_out[c >> 1][j];
        ob[(size_t)c * NPTS + j] = (c & 1) ? v.y : v.x;
    }
}

extern "C" void kernel_launch(void* const* d_in, const int* in_sizes, int n_in,
                              void* d_out, int out_size) {
    const float* x      = (const float*)d_in[0];
    const float* coords = (const float*)d_in[1];
    if (n_in >= 2 && in_sizes[0] == NB * NPTS * 2) {  // defensive swap
        const float* t = x; x = coords; coords = t;
    }
    float* out = (float*)d_out;

    transpose_kernel<<<NB * (PLANE / 64), 256>>>(x);
    gather_kernel<<<(NB * NPTS) / 32, 256>>>(coords, out);
}